// round 7
// baseline (speedup 1.0000x reference)
#include <cuda_runtime.h>
#include <cstdint>

// StochasticPool2d: x (16,96,224,224) f32, 2x2 non-overlapping windows.
// Reference: jax.random.categorical(key(42), window_vals) == Gumbel-max with
// threefry-2x32 (partitionable counter mode); output = sampled window value.
//
// B=16 C=96 H=224 W=224 -> OH=OW=112
// N_windows = 19,267,584 ; threads = N_windows/2 = 9,633,792 = 37632*256 exactly.
//
// R6: alu-pipe is the binder (89.9%): threefry SHF+LOP3 are alu-only; ptxas
// splits the adds across IMAD/IADD3. Force ALL threefry adds onto the fma
// pipe via mad.lo.u32 with an opaque multiplier (blockDim.x>>8 == 1, unknown
// to ptxas). Certificate trimmed: |g|<=17 folded into a constant bound.

static constexpr uint32_t TF_K1 = 42u;
static constexpr uint32_t TF_K2 = 0x1BD11BDAu ^ 0u ^ 42u;  // ks[2]

__device__ __forceinline__ uint32_t rotl32(uint32_t x, int d) {
    return __funnelshift_l(x, x, d);
}

// a + b, emitted as IMAD (fma pipe): a*one + b with one==1 but opaque to ptxas.
__device__ __forceinline__ uint32_t addm(uint32_t a, uint32_t b, uint32_t one) {
    uint32_t d;
    asm("mad.lo.u32 %0, %1, %2, %3;" : "=r"(d) : "r"(a), "r"(one), "r"(b));
    return d;
}

// threefry2x32, key=(0,42), counter=(0, n); returns out0 ^ out1.
// All adds routed through IMAD (addm).
__device__ __forceinline__ uint32_t threefry_bits(uint32_t n, uint32_t one) {
    uint32_t x0 = 0u;               // counter_hi + ks[0] (both 0)
    uint32_t x1 = addm(n, TF_K1, one);
#define TF_ROUND(r) { x0 = addm(x0, x1, one); x1 = rotl32(x1, (r)); x1 ^= x0; }
    TF_ROUND(13) TF_ROUND(15) TF_ROUND(26) TF_ROUND(6)
    x0 = addm(x0, TF_K1, one);      x1 = addm(x1, TF_K2 + 1u, one);
    TF_ROUND(17) TF_ROUND(29) TF_ROUND(16) TF_ROUND(24)
    x0 = addm(x0, TF_K2, one);      x1 = addm(x1, 0u + 2u, one);
    TF_ROUND(13) TF_ROUND(15) TF_ROUND(26) TF_ROUND(6)
    /* ks[0]=0 */                   x1 = addm(x1, TF_K1 + 3u, one);
    TF_ROUND(17) TF_ROUND(29) TF_ROUND(16) TF_ROUND(24)
    x0 = addm(x0, TF_K1, one);      x1 = addm(x1, TF_K2 + 4u, one);
    TF_ROUND(13) TF_ROUND(15) TF_ROUND(26) TF_ROUND(6)
    x0 = addm(x0, TF_K2, one);      x1 = addm(x1, 0u + 5u, one);
#undef TF_ROUND
    return x0 ^ x1;
}

// bits -> uniform(tiny,1), matching jax _uniform in f32 exactly.
__device__ __forceinline__ float uniform32(uint32_t bits) {
    float f = __uint_as_float((bits >> 9) | 0x3f800000u) - 1.0f;
    return fmaxf(f, 1.17549435e-38f);
}

// Exact gumbel (matches XLA f32: precise logf == __nv_logf).
__device__ __forceinline__ float gumbel_exact(float u) {
    return -logf(-logf(u));
}

__device__ __forceinline__ float rcp_approx(float x) {
    float r;
    asm("rcp.approx.f32 %0, %1;" : "=f"(r) : "f"(x));
    return r;
}

// One 2x2 window: fast gumbel-max with certified margin, exact fallback.
// Certificate: with u in [tiny, 1-2^-24], t = -log u in [1.19e-7, 88.8], so
// |g| = |log t| <= 17 and the fast-vs-exact per-value error is bounded by
//   |dg| <= 1e-6*(1+|g|) + 1e-6*max(1, 1/t) <= 1.8e-5 + 1e-6/min_t.
// We require min_t >= 1e-3 and margin > 8e-5 + 4e-6/min_t (>= 2x the bound,
// with extra slop for rcp.approx); otherwise recompute bit-exactly.
__device__ __forceinline__ float pool_window(float v0, float v1, float v2, float v3,
                                             float u0, float u1, float u2, float u3) {
    float t0 = -__logf(u0), t1 = -__logf(u1), t2 = -__logf(u2), t3 = -__logf(u3);
    float g0 = -__logf(t0), g1 = -__logf(t1), g2 = -__logf(t2), g3 = -__logf(t3);
    float s0 = v0 + g0, s1 = v1 + g1, s2 = v2 + g2, s3 = v3 + g3;

    // first-max scan with second-max tracking
    float best = s0, second = -3.4e38f, val = v0;
    if (s1 > best) { second = best; best = s1; val = v1; } else second = s1;
    if (s2 > best) { second = best; best = s2; val = v2; }
    else if (s2 > second) second = s2;
    if (s3 > best) { second = best; best = s3; val = v3; }
    else if (s3 > second) second = s3;

    float min_t = fminf(fminf(t0, t1), fminf(t2, t3));
    float E = fmaf(rcp_approx(min_t), 4e-6f, 8e-5f);

    bool certain = (min_t >= 1e-3f) && (best - second > E);
    if (!certain) {
        // Bit-exact reference path (rare).
        float G0 = gumbel_exact(u0), G1 = gumbel_exact(u1);
        float G2 = gumbel_exact(u2), G3 = gumbel_exact(u3);
        float S0 = v0 + G0, S1 = v1 + G1, S2 = v2 + G2, S3 = v3 + G3;
        float B = S0; val = v0;
        if (S1 > B) { B = S1; val = v1; }
        if (S2 > B) { B = S2; val = v2; }
        if (S3 > B) { B = S3; val = v3; }
    }
    return val;
}

__global__ void __launch_bounds__(256)
stochpool_kernel(const float* __restrict__ x, float* __restrict__ out) {
    uint32_t i = blockIdx.x * 256u + threadIdx.x;  // grid covers range exactly
    uint32_t one = blockDim.x >> 8;                // == 1, opaque to ptxas

    // Thread i handles windows 2i, 2i+1 (adjacent in ow; OW=112 even).
    uint32_t owp = i % 56u;
    uint32_t t   = i / 56u;
    uint32_t oh  = t % 112u;
    uint32_t bc  = t / 112u;  // b*96 + c

    uint32_t in_base = (bc * 224u + 2u * oh) * 224u + 4u * owp;
    float4 r0 = *reinterpret_cast<const float4*>(x + in_base);
    float4 r1 = *reinterpret_cast<const float4*>(x + in_base + 224u);

    // Window w uses gumbel counters 4w..4w+3 -> this thread: 8i..8i+7.
    uint32_t cbase = 8u * i;
    float u[8];
#pragma unroll
    for (int k = 0; k < 8; k++)
        u[k] = uniform32(threefry_bits(cbase + (uint32_t)k, one));

    // window k-index = kh*2+kw -> (r.x, r.y of row0; r.x, r.y of row1)
    float o0 = pool_window(r0.x, r0.y, r1.x, r1.y, u[0], u[1], u[2], u[3]);
    float o1 = pool_window(r0.z, r0.w, r1.z, r1.w, u[4], u[5], u[6], u[7]);

    uint32_t out_base = (bc * 112u + oh) * 112u + 2u * owp;
    *reinterpret_cast<float2*>(out + out_base) = make_float2(o0, o1);
}

extern "C" void kernel_launch(void* const* d_in, const int* in_sizes, int n_in,
                              void* d_out, int out_size) {
    const float* x = (const float*)d_in[0];
    float* out = (float*)d_out;
    (void)in_sizes; (void)n_in; (void)out_size;
    stochpool_kernel<<<37632, 256>>>(x, out);
}